// round 8
// baseline (speedup 1.0000x reference)
#include <cuda_runtime.h>
#include <math.h>

// Problem constants (match reference)
#define PW  256
#define PH  256
#define TANFOVX 0.5f
#define TANFOVY 0.5f
#define NEARP 0.2f
#define COV_BLUR 0.3f
#define ALPHA_MIN (1.0f/255.0f)
#define ALPHA_MAX 0.99f

#define P_MAX 512
#define TILE_W 16
#define TILE_H 16
#define NTHREADS 256          // 1 pixel/thread, 2 gaussians/thread
#define NWARPS (NTHREADS/32)

// ---------------------------------------------------------------------------
// Fused kernel, high-occupancy shape: each 256-thread block owns a 16x16
// tile; each thread preprocesses TWO gaussians (passes p=tid, p=tid+256).
// Survivors are compacted into shared at their compact position (params
// scattered immediately, registers released), then a depth rank-sort builds
// an index permutation; per-pixel blend walks perm[] front-to-back.
// ---------------------------------------------------------------------------
__global__ __launch_bounds__(NTHREADS, 5)
void gs_fused(const float* __restrict__ means3D,
              const float* __restrict__ opacities,
              const float* __restrict__ scales,
              const float* __restrict__ rotations,
              const float* __restrict__ colors,
              const float* __restrict__ viewm,
              const float* __restrict__ projm,
              const float* __restrict__ bg,
              float* __restrict__ out,
              int P)
{
    __shared__ float  smat[36];    // [0..15] viewm, [16..31] projm, [32..34] bg
    __shared__ float  sdep[P_MAX];
    __shared__ float4 s1[P_MAX];   // {px, py, conA, conB}  (compact order)
    __shared__ float4 s2[P_MAX];   // {conC, thr, lopa, 0}
    __shared__ float4 sc4[P_MAX];  // {r, g, b, 0}
    __shared__ int    sperm[P_MAX];
    __shared__ int warpcnt[NWARPS];
    __shared__ int warpoff[NWARPS];
    __shared__ int s_count;

    int tid  = threadIdx.x;
    int wid  = tid >> 5;
    int lane = tid & 31;

    if (tid < 36) {
        float v;
        if (tid < 16)      v = viewm[tid];
        else if (tid < 32) v = projm[tid - 16];
        else if (tid < 35) v = bg[tid - 32];
        else               v = 0.f;
        smat[tid] = v;
    }
    __syncthreads();

    float tx0 = (float)(blockIdx.x * TILE_W);
    float tx1 = tx0 + (float)(TILE_W - 1);
    float ty0 = (float)(blockIdx.y * TILE_H);
    float ty1 = ty0 + (float)(TILE_H - 1);

    int   mypos[2];  mypos[0] = -1; mypos[1] = -1;
    float mydep[2];  mydep[0] = 0.f; mydep[1] = 0.f;
    int count = 0;

    #pragma unroll
    for (int pass = 0; pass < 2; pass++) {
        int p = pass * NTHREADS + tid;
        bool pred = false;
        float pix_x = 0.f, pix_y = 0.f, conA = 0.f, conB = 0.f, conC = 0.f;
        float thr = 0.f, lopa = 0.f, depth = 0.f;
        float cl0 = 0.f, cl1 = 0.f, cl2 = 0.f;

        if (p < P) {
            float mx = means3D[3*p+0], my = means3D[3*p+1], mz = means3D[3*p+2];
            float opa_raw = opacities[p];
            float s0 = scales[3*p+0], sA = scales[3*p+1], sB = scales[3*p+2];
            float4 q4 = ((const float4*)rotations)[p];
            cl0 = colors[3*p+0]; cl1 = colors[3*p+1]; cl2 = colors[3*p+2];

            // lopa = log(sigmoid(o)) = -log(1 + e^{-o})   (no division)
            lopa = -__logf(1.0f + __expf(-opa_raw));
            thr  = __logf(ALPHA_MIN) - lopa;   // contribute iff thr <= power <= 0

            float sx = __expf(s0);
            float sy = __expf(sA);
            float sz = __expf(sB);

            float qr = q4.x, qx = q4.y, qy = q4.z, qz = q4.w;
            float qq = qr*qr + qx*qx + qy*qy + qz*qz;
            float inv = rsqrtf(fmaxf(qq, 1e-24f));
            qr *= inv; qx *= inv; qy *= inv; qz *= inv;

            float R00 = 1.f - 2.f*(qy*qy + qz*qz), R01 = 2.f*(qx*qy - qr*qz), R02 = 2.f*(qx*qz + qr*qy);
            float R10 = 2.f*(qx*qy + qr*qz), R11 = 1.f - 2.f*(qx*qx + qz*qz), R12 = 2.f*(qy*qz - qr*qx);
            float R20 = 2.f*(qx*qz - qr*qy), R21 = 2.f*(qy*qz + qr*qx), R22 = 1.f - 2.f*(qx*qx + qy*qy);

            float L00 = R00*sx, L01 = R01*sy, L02 = R02*sz;
            float L10 = R10*sx, L11 = R11*sy, L12 = R12*sz;
            float L20 = R20*sx, L21 = R21*sy, L22 = R22*sz;
            float M00 = L00*L00 + L01*L01 + L02*L02;
            float M01 = L00*L10 + L01*L11 + L02*L12;
            float M02 = L00*L20 + L01*L21 + L02*L22;
            float M11 = L10*L10 + L11*L11 + L12*L12;
            float M12 = L10*L20 + L11*L21 + L12*L22;
            float M22 = L20*L20 + L21*L21 + L22*L22;

            float tx = smat[0]*mx + smat[1]*my + smat[2] *mz + smat[3];
            float ty = smat[4]*mx + smat[5]*my + smat[6] *mz + smat[7];
            float tz = smat[8]*mx + smat[9]*my + smat[10]*mz + smat[11];

            bool valid = tz > NEARP;
            float tzc = valid ? tz : 1.0f;
            float itz = __fdividef(1.0f, tzc);

            float limx = 1.3f * TANFOVX, limy = 1.3f * TANFOVY;
            float txz = fminf(fmaxf(tx * itz, -limx), limx) * tzc;
            float tyz = fminf(fmaxf(ty * itz, -limy), limy) * tzc;

            float fx = (float)PW / (2.0f * TANFOVX);
            float fy = (float)PH / (2.0f * TANFOVY);
            float itz2 = itz * itz;
            float J00 = fx * itz,  J02 = -fx * txz * itz2;
            float J11 = fy * itz,  J12 = -fy * tyz * itz2;

            float u0 = J00*smat[0] + J02*smat[8];
            float u1 = J00*smat[1] + J02*smat[9];
            float u2 = J00*smat[2] + J02*smat[10];
            float v0 = J11*smat[4] + J12*smat[8];
            float v1 = J11*smat[5] + J12*smat[9];
            float v2 = J11*smat[6] + J12*smat[10];

            float Mu0 = M00*u0 + M01*u1 + M02*u2;
            float Mu1 = M01*u0 + M11*u1 + M12*u2;
            float Mu2 = M02*u0 + M12*u1 + M22*u2;
            float Mv0 = M00*v0 + M01*v1 + M02*v2;
            float Mv1 = M01*v0 + M11*v1 + M12*v2;
            float Mv2 = M02*v0 + M12*v1 + M22*v2;

            float c00 = u0*Mu0 + u1*Mu1 + u2*Mu2 + COV_BLUR;
            float c01 = u0*Mv0 + u1*Mv1 + u2*Mv2;
            float c11 = v0*Mv0 + v1*Mv1 + v2*Mv2 + COV_BLUR;

            float det = c00*c11 - c01*c01;
            det = (det == 0.0f) ? 1.0f : det;
            float idet = __fdividef(1.0f, det);
            conA = c11 * idet;
            conB = -c01 * idet;
            conC = c00 * idet;

            float ph0 = smat[16]*mx + smat[17]*my + smat[18]*mz + smat[19];
            float ph1 = smat[20]*mx + smat[21]*my + smat[22]*mz + smat[23];
            float ph3 = smat[28]*mx + smat[29]*my + smat[30]*mz + smat[31];
            float pw  = __fdividef(1.0f, ph3 + 1e-7f);
            pix_x = ((ph0 * pw + 1.0f) * (float)PW - 1.0f) * 0.5f;
            pix_y = ((ph1 * pw + 1.0f) * (float)PH - 1.0f) * 0.5f;

            depth = tz;

            if (valid && thr <= 0.0f) {
                float tau = -thr;
                float ex = sqrtf(2.0f * tau * c00);
                float ey = sqrtf(2.0f * tau * c11);
                pred = (pix_x - ex <= tx1) && (pix_x + ex >= tx0) &&
                       (pix_y - ey <= ty1) && (pix_y + ey >= ty0);
            }
        }

        // compact (index order preserved within + across passes)
        unsigned m = __ballot_sync(0xffffffffu, pred);
        if (lane == 0) warpcnt[wid] = __popc(m);
        __syncthreads();
        if (tid == 0) {
            int acc = count;
            #pragma unroll
            for (int w = 0; w < NWARPS; w++) { warpoff[w] = acc; acc += warpcnt[w]; }
            s_count = acc;
        }
        __syncthreads();
        if (pred) {
            int pos = warpoff[wid] + __popc(m & ((1u << lane) - 1u));
            sdep[pos] = depth;
            s1[pos]  = make_float4(pix_x, pix_y, conA, conB);
            s2[pos]  = make_float4(conC, thr, lopa, 0.0f);
            sc4[pos] = make_float4(cl0, cl1, cl2, 0.0f);
            mypos[pass] = pos;
            mydep[pass] = depth;
        }
        __syncthreads();
        count = s_count;
    }

    // ---- rank-sort survivors -> permutation (stable via compact index) ----
    #pragma unroll
    for (int pass = 0; pass < 2; pass++) {
        int pos = mypos[pass];
        if (pos >= 0) {
            float depth = mydep[pass];
            int rank = 0;
            for (int j = 0; j < count; j++) {
                float dj = sdep[j];
                rank += (dj < depth) || (dj == depth && j < pos);
            }
            sperm[rank] = pos;
        }
    }
    __syncthreads();

    // ---- per-pixel front-to-back blend over sorted survivors ----
    int lx = tid & (TILE_W - 1);
    int ly = tid >> 4;
    float fpx = tx0 + (float)lx;
    float fpy = ty0 + (float)ly;

    float T = 1.0f, cr = 0.0f, cg = 0.0f, cb = 0.0f;

    for (int i = 0; i < count; i++) {
        int idx = sperm[i];
        float4 a = s1[idx];               // px, py, A, B
        float dx = a.x - fpx;
        float dy = a.y - fpy;
        float4 b = s2[idx];               // C, thr, lopa
        float power = -0.5f * (a.z * dx * dx + b.x * dy * dy) - a.w * dx * dy;
        if (power > 0.0f || power < b.y) continue;
        float alpha = fminf(ALPHA_MAX, __expf(power + b.z));
        float4 c = sc4[idx];
        float w = alpha * T;
        cr += w * c.x;
        cg += w * c.y;
        cb += w * c.z;
        T *= (1.0f - alpha);
        if (T < 1e-4f) break;             // residual weight <= 1e-4 (within tol)
    }

    float b0 = smat[32], b1 = smat[33], b2 = smat[34];
    int x = blockIdx.x * TILE_W + lx;
    int y = blockIdx.y * TILE_H + ly;
    int o = (y * PW + x) * 3;
    out[o + 0] = cr + T * b0;
    out[o + 1] = cg + T * b1;
    out[o + 2] = cb + T * b2;
}

// ---------------------------------------------------------------------------
extern "C" void kernel_launch(void* const* d_in, const int* in_sizes, int n_in,
                              void* d_out, int out_size)
{
    const float* means3D   = (const float*)d_in[0];
    const float* opacities = (const float*)d_in[1];
    const float* scales    = (const float*)d_in[2];
    const float* rotations = (const float*)d_in[3];
    const float* colors    = (const float*)d_in[4];
    const float* viewm     = (const float*)d_in[5];
    const float* projm     = (const float*)d_in[6];
    // d_in[7] = campos (unused), d_in[8] = bg
    const float* bg        = (const float*)d_in[8];
    float* out = (float*)d_out;

    int P = in_sizes[0] / 3;
    if (P > P_MAX) P = P_MAX;

    dim3 grid(PW / TILE_W, PH / TILE_H);   // 16 x 16 = 256 blocks
    gs_fused<<<grid, NTHREADS>>>(means3D, opacities, scales, rotations, colors,
                                 viewm, projm, bg, out, P);
}

// round 9
// speedup vs baseline: 1.1916x; 1.1916x over previous
#include <cuda_runtime.h>
#include <math.h>

// Problem constants (match reference)
#define PW  256
#define PH  256
#define TANFOVX 0.5f
#define TANFOVY 0.5f
#define NEARP 0.2f
#define COV_BLUR 0.3f
#define ALPHA_MIN (1.0f/255.0f)
#define ALPHA_MAX 0.99f

#define P_MAX 512
#define TILE_W 16
#define TILE_H 16
#define NPIX (TILE_W*TILE_H)     // 256 pixels per tile
#define NTHREADS 512             // 2 threads per pixel (front/back list halves)
#define NWARPS (NTHREADS/32)

// ---------------------------------------------------------------------------
// Fused kernel: each block (16x16 tile) preprocesses all P gaussians
// (1/thread), compacts + rank-sorts survivors by depth, then composites with
// a 2-way list split. Blend inner loop is fully branchless (predicated
// alpha, unconditional accumulate) with a warp-collective early-out every 8
// iterations — eliminates per-iteration BSSY/BSYNC divergence cost.
// ---------------------------------------------------------------------------
__global__ __launch_bounds__(NTHREADS, 2)
void gs_fused(const float* __restrict__ means3D,
              const float* __restrict__ opacities,
              const float* __restrict__ scales,
              const float* __restrict__ rotations,
              const float* __restrict__ colors,
              const float* __restrict__ viewm,
              const float* __restrict__ projm,
              const float* __restrict__ bg,
              float* __restrict__ out,
              int P)
{
    __shared__ float  smat[36];    // [0..15] viewm, [16..31] projm, [32..34] bg
    __shared__ float  sdep[P_MAX];
    __shared__ float4 s1[P_MAX];   // {px, py, conA, conB}
    __shared__ float4 s2[P_MAX];   // {conC, thr, lopa, 0}
    __shared__ float4 sc[P_MAX];   // {r, g, b, 0}
    __shared__ float4 sback[NPIX]; // back-half partials {r,g,b,T}
    __shared__ int warpcnt[NWARPS];
    __shared__ int warpoff[NWARPS];
    __shared__ int s_count;

    int tid  = threadIdx.x;
    int wid  = tid >> 5;
    int lane = tid & 31;

    // ---- Hoisted per-gaussian loads ----
    int p = tid;
    float mx = 0.f, my = 0.f, mz = 0.f, opa_raw = 0.f;
    float sc0 = 0.f, sc1 = 0.f, sc2 = 0.f;
    float4 q4 = make_float4(1.f, 0.f, 0.f, 0.f);
    float cl0 = 0.f, cl1 = 0.f, cl2 = 0.f;
    if (p < P) {
        mx = means3D[3*p+0]; my = means3D[3*p+1]; mz = means3D[3*p+2];
        opa_raw = opacities[p];
        sc0 = scales[3*p+0]; sc1 = scales[3*p+1]; sc2 = scales[3*p+2];
        q4 = ((const float4*)rotations)[p];
        cl0 = colors[3*p+0]; cl1 = colors[3*p+1]; cl2 = colors[3*p+2];
    }

    // ---- Stage uniforms ----
    if (tid < 36) {
        float v;
        if (tid < 16)      v = viewm[tid];
        else if (tid < 32) v = projm[tid - 16];
        else if (tid < 35) v = bg[tid - 32];
        else               v = 0.f;
        smat[tid] = v;
    }
    __syncthreads();

    float tx0 = (float)(blockIdx.x * TILE_W);
    float tx1 = tx0 + (float)(TILE_W - 1);
    float ty0 = (float)(blockIdx.y * TILE_H);
    float ty1 = ty0 + (float)(TILE_H - 1);

    // ---- Preprocess my gaussian ----
    bool  pred  = false;
    float pix_x = 0.f, pix_y = 0.f, conA = 0.f, conB = 0.f, conC = 0.f;
    float thr = 0.f, lopa = 0.f, depth = 0.f;

    if (p < P) {
        // lopa = log(sigmoid(o)) = -log(1 + e^{-o})
        lopa = -__logf(1.0f + __expf(-opa_raw));
        thr  = __logf(ALPHA_MIN) - lopa;   // contribute iff thr <= power <= 0

        float sx = __expf(sc0);
        float sy = __expf(sc1);
        float sz = __expf(sc2);

        float qr = q4.x, qx = q4.y, qy = q4.z, qz = q4.w;
        float qq = qr*qr + qx*qx + qy*qy + qz*qz;
        float inv = rsqrtf(fmaxf(qq, 1e-24f));
        qr *= inv; qx *= inv; qy *= inv; qz *= inv;

        float R00 = 1.f - 2.f*(qy*qy + qz*qz), R01 = 2.f*(qx*qy - qr*qz), R02 = 2.f*(qx*qz + qr*qy);
        float R10 = 2.f*(qx*qy + qr*qz), R11 = 1.f - 2.f*(qx*qx + qz*qz), R12 = 2.f*(qy*qz - qr*qx);
        float R20 = 2.f*(qx*qz - qr*qy), R21 = 2.f*(qy*qz + qr*qx), R22 = 1.f - 2.f*(qx*qx + qy*qy);

        float L00 = R00*sx, L01 = R01*sy, L02 = R02*sz;
        float L10 = R10*sx, L11 = R11*sy, L12 = R12*sz;
        float L20 = R20*sx, L21 = R21*sy, L22 = R22*sz;
        float M00 = L00*L00 + L01*L01 + L02*L02;
        float M01 = L00*L10 + L01*L11 + L02*L12;
        float M02 = L00*L20 + L01*L21 + L02*L22;
        float M11 = L10*L10 + L11*L11 + L12*L12;
        float M12 = L10*L20 + L11*L21 + L12*L22;
        float M22 = L20*L20 + L21*L21 + L22*L22;

        float tx = smat[0]*mx + smat[1]*my + smat[2] *mz + smat[3];
        float ty = smat[4]*mx + smat[5]*my + smat[6] *mz + smat[7];
        float tz = smat[8]*mx + smat[9]*my + smat[10]*mz + smat[11];

        bool valid = tz > NEARP;
        float tzc = valid ? tz : 1.0f;
        float itz = __fdividef(1.0f, tzc);

        float limx = 1.3f * TANFOVX, limy = 1.3f * TANFOVY;
        float txz = fminf(fmaxf(tx * itz, -limx), limx) * tzc;
        float tyz = fminf(fmaxf(ty * itz, -limy), limy) * tzc;

        float fx = (float)PW / (2.0f * TANFOVX);
        float fy = (float)PH / (2.0f * TANFOVY);
        float itz2 = itz * itz;
        float J00 = fx * itz,  J02 = -fx * txz * itz2;
        float J11 = fy * itz,  J12 = -fy * tyz * itz2;

        float u0 = J00*smat[0] + J02*smat[8];
        float u1 = J00*smat[1] + J02*smat[9];
        float u2 = J00*smat[2] + J02*smat[10];
        float v0 = J11*smat[4] + J12*smat[8];
        float v1 = J11*smat[5] + J12*smat[9];
        float v2 = J11*smat[6] + J12*smat[10];

        float Mu0 = M00*u0 + M01*u1 + M02*u2;
        float Mu1 = M01*u0 + M11*u1 + M12*u2;
        float Mu2 = M02*u0 + M12*u1 + M22*u2;
        float Mv0 = M00*v0 + M01*v1 + M02*v2;
        float Mv1 = M01*v0 + M11*v1 + M12*v2;
        float Mv2 = M02*v0 + M12*v1 + M22*v2;

        float c00 = u0*Mu0 + u1*Mu1 + u2*Mu2 + COV_BLUR;
        float c01 = u0*Mv0 + u1*Mv1 + u2*Mv2;
        float c11 = v0*Mv0 + v1*Mv1 + v2*Mv2 + COV_BLUR;

        float det = c00*c11 - c01*c01;
        det = (det == 0.0f) ? 1.0f : det;
        float idet = __fdividef(1.0f, det);
        conA = c11 * idet;
        conB = -c01 * idet;
        conC = c00 * idet;

        float ph0 = smat[16]*mx + smat[17]*my + smat[18]*mz + smat[19];
        float ph1 = smat[20]*mx + smat[21]*my + smat[22]*mz + smat[23];
        float ph3 = smat[28]*mx + smat[29]*my + smat[30]*mz + smat[31];
        float pw  = __fdividef(1.0f, ph3 + 1e-7f);
        pix_x = ((ph0 * pw + 1.0f) * (float)PW - 1.0f) * 0.5f;
        pix_y = ((ph1 * pw + 1.0f) * (float)PH - 1.0f) * 0.5f;

        depth = tz;

        if (valid && thr <= 0.0f) {
            float tau = -thr;
            float ex = sqrtf(2.0f * tau * c00);
            float ey = sqrtf(2.0f * tau * c11);
            pred = (pix_x - ex <= tx1) && (pix_x + ex >= tx0) &&
                   (pix_y - ey <= ty1) && (pix_y + ey >= ty0);
        }
    }

    // ---- Compact survivors (original index order preserved) ----
    unsigned m = __ballot_sync(0xffffffffu, pred);
    if (lane == 0) warpcnt[wid] = __popc(m);
    __syncthreads();
    if (tid == 0) {
        int acc = 0;
        #pragma unroll
        for (int w = 0; w < NWARPS; w++) { warpoff[w] = acc; acc += warpcnt[w]; }
        s_count = acc;
    }
    __syncthreads();

    int pos = 0;
    if (pred) {
        pos = warpoff[wid] + __popc(m & ((1u << lane) - 1u));
        sdep[pos] = depth;
    }
    __syncthreads();
    int count = s_count;

    // ---- Rank-sort survivors by depth (stable via compact index) ----
    if (pred) {
        int rank = 0;
        for (int j = 0; j < count; j++) {
            float dj = sdep[j];
            rank += (dj < depth) || (dj == depth && j < pos);
        }
        s1[rank] = make_float4(pix_x, pix_y, conA, conB);
        s2[rank] = make_float4(conC, thr, lopa, 0.0f);
        sc[rank] = make_float4(cl0, cl1, cl2, 0.0f);
    }
    __syncthreads();

    // ---- Split-list branchless blend: 2 threads per pixel ----
    int pix      = tid & (NPIX - 1);
    int half_sel = tid >> 8;            // 0 = front half, 1 = back half
    int lx = pix & (TILE_W - 1);
    int ly = pix / TILE_W;
    float fpx = tx0 + (float)lx;
    float fpy = ty0 + (float)ly;

    int halfc = (count + 1) >> 1;
    int i0 = half_sel ? halfc : 0;
    int i1 = half_sel ? count : halfc;

    float T = 1.0f, cr = 0.0f, cg = 0.0f, cb = 0.0f;

    int i = i0;
    while (i < i1) {
        int stop = min(i + 8, i1);
        #pragma unroll 8
        for (; i < stop; i++) {
            float4 a = s1[i];             // px, py, A, B
            float4 b = s2[i];             // C, thr, lopa
            float4 c = sc[i];
            float dx = a.x - fpx;
            float dy = a.y - fpy;
            float power = -0.5f * (a.z * dx * dx + b.x * dy * dy) - a.w * dx * dy;
            float alpha = fminf(ALPHA_MAX, __expf(power + b.z));
            // predicated zero: miss (outside band) contributes nothing
            alpha = (power > 0.0f || power < b.y) ? 0.0f : alpha;
            float w = alpha * T;
            cr += w * c.x;
            cg += w * c.y;
            cb += w * c.z;
            T *= (1.0f - alpha);
        }
        // warp-collective early-out: uniform branch, no divergence
        if (__all_sync(0xffffffffu, T < 1e-4f)) break;
    }

    if (half_sel) {
        sback[pix] = make_float4(cr, cg, cb, T);
    }
    __syncthreads();

    if (!half_sel) {
        float4 bk = sback[pix];
        cr += T * bk.x;
        cg += T * bk.y;
        cb += T * bk.z;
        T  *= bk.w;

        float b0 = smat[32], b1 = smat[33], b2 = smat[34];
        int x = blockIdx.x * TILE_W + lx;
        int y = blockIdx.y * TILE_H + ly;
        int o = (y * PW + x) * 3;
        out[o + 0] = cr + T * b0;
        out[o + 1] = cg + T * b1;
        out[o + 2] = cb + T * b2;
    }
}

// ---------------------------------------------------------------------------
extern "C" void kernel_launch(void* const* d_in, const int* in_sizes, int n_in,
                              void* d_out, int out_size)
{
    const float* means3D   = (const float*)d_in[0];
    const float* opacities = (const float*)d_in[1];
    const float* scales    = (const float*)d_in[2];
    const float* rotations = (const float*)d_in[3];
    const float* colors    = (const float*)d_in[4];
    const float* viewm     = (const float*)d_in[5];
    const float* projm     = (const float*)d_in[6];
    // d_in[7] = campos (unused), d_in[8] = bg
    const float* bg        = (const float*)d_in[8];
    float* out = (float*)d_out;

    int P = in_sizes[0] / 3;
    if (P > P_MAX) P = P_MAX;

    dim3 grid(PW / TILE_W, PH / TILE_H);   // 16 x 16 = 256 blocks
    gs_fused<<<grid, NTHREADS>>>(means3D, opacities, scales, rotations, colors,
                                 viewm, projm, bg, out, P);
}